// round 1
// baseline (speedup 1.0000x reference)
#include <cuda_runtime.h>
#include <cuda_bf16.h>

// Problem constants
#define B_  8
#define T_  1024
#define C_  768
#define H_  12
#define HS_ 64
#define M_TOT (B_*T_)        // 8192
#define N_TOT (3*C_)         // 2304
#define K_TOT C_             // 768

// Scratch: Q/K/V in [B,H,T,hs] layout (fp32). 3 x 24 MB device globals.
__device__ float g_Q[B_*H_*T_*HS_];
__device__ float g_K[B_*H_*T_*HS_];
__device__ float g_V[B_*H_*T_*HS_];

// ---------------------------------------------------------------------------
// Kernel 1: fused QKV projection.  out[m,n] = sum_k x[m,k] * W[n,k] + b[n]
// scattered into g_Q / g_K / g_V in [B,H,T,hs] layout.
// 64x64 tile, BK=16, 256 threads, 4x4 per-thread fragment.
// ---------------------------------------------------------------------------
__global__ __launch_bounds__(256) void qkv_gemm_kernel(
    const float* __restrict__ x,      // [8192, 768]
    const float* __restrict__ W,      // [2304, 768]
    const float* __restrict__ bias)   // [2304]
{
    __shared__ float As[16][68];   // [k][m], padded
    __shared__ float Bs[16][68];   // [k][n], padded

    const int tx = threadIdx.x & 15;       // 0..15  -> n frag
    const int ty = threadIdx.x >> 4;       // 0..15  -> m frag
    const int m0 = blockIdx.y * 64;
    const int n0 = blockIdx.x * 64;

    const int lr  = threadIdx.x >> 2;        // 0..63 row for loading
    const int lc4 = (threadIdx.x & 3) * 4;   // 0,4,8,12

    float acc[4][4] = {};

    for (int k0 = 0; k0 < K_TOT; k0 += 16) {
        // Load A tile (64 x 16) transposed into As[k][m]
        {
            const float4 av = *reinterpret_cast<const float4*>(
                x + (size_t)(m0 + lr) * K_TOT + k0 + lc4);
            As[lc4 + 0][lr] = av.x;
            As[lc4 + 1][lr] = av.y;
            As[lc4 + 2][lr] = av.z;
            As[lc4 + 3][lr] = av.w;
            const float4 bv = *reinterpret_cast<const float4*>(
                W + (size_t)(n0 + lr) * K_TOT + k0 + lc4);
            Bs[lc4 + 0][lr] = bv.x;
            Bs[lc4 + 1][lr] = bv.y;
            Bs[lc4 + 2][lr] = bv.z;
            Bs[lc4 + 3][lr] = bv.w;
        }
        __syncthreads();

        #pragma unroll
        for (int kk = 0; kk < 16; kk++) {
            const float4 a = *reinterpret_cast<const float4*>(&As[kk][ty * 4]);
            const float4 b = *reinterpret_cast<const float4*>(&Bs[kk][tx * 4]);
            const float ar[4] = {a.x, a.y, a.z, a.w};
            const float br[4] = {b.x, b.y, b.z, b.w};
            #pragma unroll
            for (int i = 0; i < 4; i++)
                #pragma unroll
                for (int j = 0; j < 4; j++)
                    acc[i][j] = fmaf(ar[i], br[j], acc[i][j]);
        }
        __syncthreads();
    }

    // Epilogue: bias add + scatter to Q/K/V.
    // Tile is 64 wide => entirely within one (three, head) slice.
    const int nbase = n0 + tx * 4;
    const int three = nbase / C_;            // 0,1,2
    const int rem   = nbase % C_;
    const int head  = rem >> 6;              // /64
    const int dbase = rem & 63;
    float* dst = (three == 0) ? g_Q : (three == 1) ? g_K : g_V;

    #pragma unroll
    for (int i = 0; i < 4; i++) {
        const int m = m0 + ty * 4 + i;
        const int bb = m >> 10;               // /1024
        const int t  = m & 1023;
        float4 v;
        v.x = acc[i][0] + bias[nbase + 0];
        v.y = acc[i][1] + bias[nbase + 1];
        v.z = acc[i][2] + bias[nbase + 2];
        v.w = acc[i][3] + bias[nbase + 3];
        float* p = dst + (((size_t)(bb * H_ + head) * T_ + t) * HS_ + dbase);
        *reinterpret_cast<float4*>(p) = v;
    }
}

// ---------------------------------------------------------------------------
// Kernel 2: causal ReLU attention, fused per (b, h, 64-query tile).
//   y[q,d] += relu(scale * Q[q,:] . K[k,:]) * V[k,d]   for k <= q
// 64x64 tiles over keys, no softmax bookkeeping needed (ReLU attention).
// Dynamic smem: Qs[d][q] | Ks[d][k] | Vs[k][d] | Ss[q][k]  (4 x 16 KB).
// ---------------------------------------------------------------------------
__global__ __launch_bounds__(256) void attn_kernel(float* __restrict__ out)
{
    extern __shared__ float smem[];
    float* Qs = smem;            // [d][q]  64*64
    float* Ks = smem + 4096;     // [d][k]
    float* Vs = smem + 8192;     // [k][d]
    float* Ss = smem + 12288;    // [q][k]

    const int bh = blockIdx.x;           // 0..95
    const int b  = bh / H_;
    const int h  = bh % H_;
    const int qt = blockIdx.y;           // 0..15

    const int tx = threadIdx.x & 15;
    const int ty = threadIdx.x >> 4;

    const int lq  = threadIdx.x >> 2;        // 0..63
    const int lc  = (threadIdx.x & 3) * 4;   // 0,4,8,12 (then +16*l)

    const float scale = 0.125f;              // 1/sqrt(64)

    const size_t head_base = ((size_t)(b * H_ + h)) * T_ * HS_;
    const float* qbase = g_Q + head_base + (size_t)qt * 64 * HS_;

    // Load Q tile transposed: Qs[d][q]
    #pragma unroll
    for (int l = 0; l < 4; l++) {
        const int d4 = lc + l * 16;
        const float4 v = *reinterpret_cast<const float4*>(qbase + lq * HS_ + d4);
        Qs[(d4 + 0) * 64 + lq] = v.x;
        Qs[(d4 + 1) * 64 + lq] = v.y;
        Qs[(d4 + 2) * 64 + lq] = v.z;
        Qs[(d4 + 3) * 64 + lq] = v.w;
    }

    float y[4][4] = {};

    for (int kt = 0; kt <= qt; kt++) {
        const float* kbase = g_K + head_base + (size_t)kt * 64 * HS_;
        const float* vbase = g_V + head_base + (size_t)kt * 64 * HS_;

        // Load K transposed Ks[d][k], V natural Vs[k][d]
        #pragma unroll
        for (int l = 0; l < 4; l++) {
            const int d4 = lc + l * 16;
            const float4 kv = *reinterpret_cast<const float4*>(kbase + lq * HS_ + d4);
            Ks[(d4 + 0) * 64 + lq] = kv.x;
            Ks[(d4 + 1) * 64 + lq] = kv.y;
            Ks[(d4 + 2) * 64 + lq] = kv.z;
            Ks[(d4 + 3) * 64 + lq] = kv.w;
            const float4 vv = *reinterpret_cast<const float4*>(vbase + lq * HS_ + d4);
            *reinterpret_cast<float4*>(Vs + lq * 64 + d4) = vv;
        }
        __syncthreads();

        // S = Q . K^T  (per-thread 4x4 fragment)
        float s[4][4] = {};
        #pragma unroll
        for (int d = 0; d < 64; d++) {
            const float4 a = *reinterpret_cast<const float4*>(Qs + d * 64 + ty * 4);
            const float4 bb = *reinterpret_cast<const float4*>(Ks + d * 64 + tx * 4);
            const float ar[4] = {a.x, a.y, a.z, a.w};
            const float br[4] = {bb.x, bb.y, bb.z, bb.w};
            #pragma unroll
            for (int i = 0; i < 4; i++)
                #pragma unroll
                for (int j = 0; j < 4; j++)
                    s[i][j] = fmaf(ar[i], br[j], s[i][j]);
        }

        // mask (causal) + relu, write Ss[q][k] (float4 row stores)
        const bool diag = (kt == qt);
        #pragma unroll
        for (int i = 0; i < 4; i++) {
            const int q = ty * 4 + i;
            float4 v;
            float* sv = &v.x;
            #pragma unroll
            for (int j = 0; j < 4; j++) {
                const int k = tx * 4 + j;
                float val = fmaxf(s[i][j] * scale, 0.0f);
                if (diag && k > q) val = 0.0f;
                sv[j] = val;
            }
            *reinterpret_cast<float4*>(Ss + q * 64 + tx * 4) = v;
        }
        __syncthreads();

        // y += Ss @ Vs
        #pragma unroll
        for (int k = 0; k < 64; k++) {
            const float a0 = Ss[(ty * 4 + 0) * 64 + k];
            const float a1 = Ss[(ty * 4 + 1) * 64 + k];
            const float a2 = Ss[(ty * 4 + 2) * 64 + k];
            const float a3 = Ss[(ty * 4 + 3) * 64 + k];
            const float4 vv = *reinterpret_cast<const float4*>(Vs + k * 64 + tx * 4);
            const float vr[4] = {vv.x, vv.y, vv.z, vv.w};
            #pragma unroll
            for (int j = 0; j < 4; j++) {
                y[0][j] = fmaf(a0, vr[j], y[0][j]);
                y[1][j] = fmaf(a1, vr[j], y[1][j]);
                y[2][j] = fmaf(a2, vr[j], y[2][j]);
                y[3][j] = fmaf(a3, vr[j], y[3][j]);
            }
        }
        __syncthreads();
    }

    // Write out[b, t, h*64 + d]  (float4 per row fragment)
    #pragma unroll
    for (int i = 0; i < 4; i++) {
        const int t = qt * 64 + ty * 4 + i;
        float4 v;
        v.x = y[i][0]; v.y = y[i][1]; v.z = y[i][2]; v.w = y[i][3];
        float* p = out + ((size_t)b * T_ + t) * C_ + h * HS_ + tx * 4;
        *reinterpret_cast<float4*>(p) = v;
    }
}

// ---------------------------------------------------------------------------
extern "C" void kernel_launch(void* const* d_in, const int* in_sizes, int n_in,
                              void* d_out, int out_size)
{
    const float* x    = (const float*)d_in[0];   // [8,1024,768]
    const float* W    = (const float*)d_in[1];   // [2304,768]
    const float* bias = (const float*)d_in[2];   // [2304]
    float* out = (float*)d_out;                  // [8,1024,768]

    // QKV projection: grid (N/64, M/64) = (36, 128)
    qkv_gemm_kernel<<<dim3(N_TOT / 64, M_TOT / 64), 256>>>(x, W, bias);

    // Attention: grid (B*H, T/64) = (96, 16), 64 KB dynamic smem
    cudaFuncSetAttribute(attn_kernel,
                         cudaFuncAttributeMaxDynamicSharedMemorySize, 65536);
    attn_kernel<<<dim3(B_ * H_, T_ / 64), 256, 65536>>>(out);
}

// round 3
// speedup vs baseline: 1.5395x; 1.5395x over previous
#include <cuda_runtime.h>
#include <cuda_bf16.h>
#include <cstdint>

// Problem constants
#define B_  8
#define T_  1024
#define C_  768
#define H_  12
#define HS_ 64
#define M_TOT (B_*T_)        // 8192
#define N_TOT (3*C_)         // 2304
#define K_TOT C_             // 768

// ---------------------------------------------------------------------------
// Device-global scratch
// ---------------------------------------------------------------------------
__device__ float g_Q[B_*H_*T_*HS_];
__device__ float g_K[B_*H_*T_*HS_];
__device__ float g_V[B_*H_*T_*HS_];

__device__ __align__(16) __nv_bfloat16 g_xh[M_TOT*K_TOT];
__device__ __align__(16) __nv_bfloat16 g_xl[M_TOT*K_TOT];
__device__ __align__(16) __nv_bfloat16 g_wh[N_TOT*K_TOT];
__device__ __align__(16) __nv_bfloat16 g_wl[N_TOT*K_TOT];

// ---------------------------------------------------------------------------
// Small PTX helpers (all base-ISA: sm_80-level, no 'a'-suffix features)
// ---------------------------------------------------------------------------
__device__ __forceinline__ uint32_t smem_u32(const void* p) {
    uint32_t a;
    asm("{ .reg .u64 t; cvta.to.shared.u64 t, %1; cvt.u32.u64 %0, t; }"
        : "=r"(a) : "l"(p));
    return a;
}

__device__ __forceinline__ void cp_async16(uint32_t s, const void* g) {
    asm volatile("cp.async.cg.shared.global [%0], [%1], 16;" :: "r"(s), "l"(g));
}
__device__ __forceinline__ void cp_commit() {
    asm volatile("cp.async.commit_group;" ::: "memory");
}
__device__ __forceinline__ void cp_wait1() {
    asm volatile("cp.async.wait_group 1;" ::: "memory");
}
__device__ __forceinline__ void cp_wait0() {
    asm volatile("cp.async.wait_group 0;" ::: "memory");
}

__device__ __forceinline__ void ldmatrix_x4(uint32_t& r0, uint32_t& r1,
                                            uint32_t& r2, uint32_t& r3,
                                            uint32_t addr) {
    asm volatile("ldmatrix.sync.aligned.m8n8.x4.shared.b16 {%0,%1,%2,%3}, [%4];"
                 : "=r"(r0), "=r"(r1), "=r"(r2), "=r"(r3) : "r"(addr));
}

__device__ __forceinline__ void mma_bf16(float& c0, float& c1, float& c2, float& c3,
                                         uint32_t a0, uint32_t a1, uint32_t a2, uint32_t a3,
                                         uint32_t b0, uint32_t b1) {
    asm volatile(
        "mma.sync.aligned.m16n8k16.row.col.f32.bf16.bf16.f32 "
        "{%0,%1,%2,%3}, {%4,%5,%6,%7}, {%8,%9}, {%0,%1,%2,%3};"
        : "+f"(c0), "+f"(c1), "+f"(c2), "+f"(c3)
        : "r"(a0), "r"(a1), "r"(a2), "r"(a3), "r"(b0), "r"(b1));
}

// ---------------------------------------------------------------------------
// Kernel 0: fp32 -> (bf16 hi, bf16 lo) split for x and W
// ---------------------------------------------------------------------------
__global__ __launch_bounds__(256) void split_kernel(const float* __restrict__ x,
                                                    const float* __restrict__ W)
{
    const int nqx = (M_TOT * K_TOT) / 4;
    const int nqw = (N_TOT * K_TOT) / 4;
    for (int q = blockIdx.x * blockDim.x + threadIdx.x; q < nqx + nqw;
         q += gridDim.x * blockDim.x) {
        const float4* src; __nv_bfloat16 *dh, *dl; int qq;
        if (q < nqx) { src = (const float4*)x; dh = g_xh; dl = g_xl; qq = q; }
        else         { src = (const float4*)W; dh = g_wh; dl = g_wl; qq = q - nqx; }
        const float4 v = src[qq];
        __nv_bfloat16 h0 = __float2bfloat16(v.x);
        __nv_bfloat16 h1 = __float2bfloat16(v.y);
        __nv_bfloat16 h2 = __float2bfloat16(v.z);
        __nv_bfloat16 h3 = __float2bfloat16(v.w);
        __nv_bfloat16 l0 = __float2bfloat16(v.x - __bfloat162float(h0));
        __nv_bfloat16 l1 = __float2bfloat16(v.y - __bfloat162float(h1));
        __nv_bfloat16 l2 = __float2bfloat16(v.z - __bfloat162float(h2));
        __nv_bfloat16 l3 = __float2bfloat16(v.w - __bfloat162float(h3));
        __nv_bfloat162* ph = (__nv_bfloat162*)(dh + (size_t)qq * 4);
        __nv_bfloat162* pl = (__nv_bfloat162*)(dl + (size_t)qq * 4);
        ph[0] = __halves2bfloat162(h0, h1);
        ph[1] = __halves2bfloat162(h2, h3);
        pl[0] = __halves2bfloat162(l0, l1);
        pl[1] = __halves2bfloat162(l2, l3);
    }
}

// ---------------------------------------------------------------------------
// Kernel 1: HMMA (mma.sync bf16) QKV GEMM, bf16-split x3.
// CTA tile 128x128, BK=32, 256 threads = 8 warps (2m x 4n), warp tile 64x32.
// Smem rows use 80-byte stride (40 bf16): conflict-free for ldmatrix.
// ---------------------------------------------------------------------------
#define ROWB 80            // bytes per smem row (32 bf16 data + pad)
#define TILE_B (128*ROWB)  // 10240 bytes per operand tile
#define BUF_B  (2*TILE_B)  // A+B per buffer
#define NITER  72          // 3 passes * 24 k-chunks

__global__ __launch_bounds__(256) void qkv_hmma_kernel(const float* __restrict__ bias)
{
    __shared__ __align__(16) char sm[2 * BUF_B];   // 40960 B

    const int tid  = threadIdx.x;
    const int warp = tid >> 5;
    const int lane = tid & 31;
    const int m0 = blockIdx.y * 128;
    const int n0 = blockIdx.x * 128;

    const int wm0 = (warp >> 2) * 64;   // warp m offset in tile
    const int wn0 = (warp & 3) * 32;    // warp n offset in tile

    const uint32_t sbase = smem_u32(sm);

    // ---- fill helper (lambda): one 32-wide k-chunk of A(128x32) + B(128x32)
    auto fill = [&](int it, int buf) {
        const int pass = it / 24;
        const int kc   = (it - pass * 24) * 32;
        const __nv_bfloat16* Asrc = (pass < 2)  ? g_xh : g_xl;
        const __nv_bfloat16* Bsrc = (pass == 1) ? g_wl : g_wh;
        const uint32_t sA = sbase + buf * BUF_B;
        const uint32_t sB = sA + TILE_B;
        #pragma unroll
        for (int j = 0; j < 2; j++) {
            const int seg = tid + j * 256;        // 0..511
            const int r = seg >> 2, c = seg & 3;  // row 0..127, 16B chunk 0..3
            cp_async16(sA + r * ROWB + c * 16,
                       Asrc + (size_t)(m0 + r) * K_TOT + kc + c * 8);
            cp_async16(sB + r * ROWB + c * 16,
                       Bsrc + (size_t)(n0 + r) * K_TOT + kc + c * 8);
        }
        cp_commit();
    };

    float acc[4][4][4] = {};   // [mt][nt][c0..c3]

    fill(0, 0);

    for (int i = 0; i < NITER; i++) {
        const int buf = i & 1;
        if (i + 1 < NITER) fill(i + 1, buf ^ 1);
        if (i + 1 < NITER) cp_wait1(); else cp_wait0();
        __syncthreads();

        const uint32_t sA = sbase + buf * BUF_B;
        const uint32_t sB = sA + TILE_B;

        // Load B fragments: 4 n-tiles, each ldmatrix.x4 covers both k-steps
        uint32_t bf[4][4];
        #pragma unroll
        for (int nt = 0; nt < 4; nt++) {
            const int rrow = wn0 + nt * 8 + (lane & 7);
            const int col  = (lane >> 3) * 8;
            ldmatrix_x4(bf[nt][0], bf[nt][1], bf[nt][2], bf[nt][3],
                        sB + rrow * ROWB + col * 2);
        }

        // 2 k-steps x 4 m-tiles x 4 n-tiles
        #pragma unroll
        for (int ks = 0; ks < 2; ks++) {
            #pragma unroll
            for (int mt = 0; mt < 4; mt++) {
                uint32_t a0, a1, a2, a3;
                const int arow = wm0 + mt * 16 + (lane & 15);
                const int acol = ks * 16 + (lane >> 4) * 8;
                ldmatrix_x4(a0, a1, a2, a3, sA + arow * ROWB + acol * 2);
                #pragma unroll
                for (int nt = 0; nt < 4; nt++) {
                    mma_bf16(acc[mt][nt][0], acc[mt][nt][1],
                             acc[mt][nt][2], acc[mt][nt][3],
                             a0, a1, a2, a3,
                             bf[nt][ks * 2 + 0], bf[nt][ks * 2 + 1]);
                }
            }
        }
        __syncthreads();
    }

    // ---- Epilogue: bias add + scatter into g_Q/g_K/g_V ([B,H,T,hs] fp32)
    const int g = lane >> 2;        // 0..7
    const int tq = lane & 3;        // 0..3
    #pragma unroll
    for (int nt = 0; nt < 4; nt++) {
        const int n = n0 + wn0 + nt * 8 + tq * 2;
        const float b0 = __ldg(bias + n);
        const float b1 = __ldg(bias + n + 1);
        const int three = n / C_;
        const int rem   = n - three * C_;
        const int head  = rem >> 6;
        const int d     = rem & 63;
        float* dst = (three == 0) ? g_Q : (three == 1) ? g_K : g_V;
        #pragma unroll
        for (int mt = 0; mt < 4; mt++) {
            #pragma unroll
            for (int half = 0; half < 2; half++) {
                const int m = m0 + wm0 + mt * 16 + g + half * 8;
                const int bb = m >> 10;
                const int t  = m & 1023;
                float2 v;
                v.x = acc[mt][nt][half * 2 + 0] + b0;
                v.y = acc[mt][nt][half * 2 + 1] + b1;
                *reinterpret_cast<float2*>(
                    g_Q + 0,  // dummy to keep type; replaced below
                    0) ;
                float* p = dst + (((size_t)(bb * H_ + head) * T_ + t) * HS_ + d);
                *reinterpret_cast<float2*>(p) = v;
            }
        }
    }
}

// ---------------------------------------------------------------------------
// Kernel 2: causal ReLU attention (unchanged fp32 version)
// ---------------------------------------------------------------------------
__global__ __launch_bounds__(256) void attn_kernel(float* __restrict__ out)
{
    extern __shared__ float smemf[];
    float* Qs = smemf;
    float* Ks = smemf + 4096;
    float* Vs = smemf + 8192;
    float* Ss = smemf + 12288;

    const int bh = blockIdx.x;
    const int b  = bh / H_;
    const int h  = bh % H_;
    const int qt = blockIdx.y;

    const int tx = threadIdx.x & 15;
    const int ty = threadIdx.x >> 4;
    const int lq  = threadIdx.x >> 2;
    const int lc  = (threadIdx.x & 3) * 4;

    const float scale = 0.125f;

    const size_t head_base = ((size_t)(b * H_ + h)) * T_ * HS_;
    const float* qbase = g_Q + head_base + (size_t)qt * 64 * HS_;

    #pragma unroll
    for (int l = 0; l < 4; l++) {
        const int d4 = lc + l * 16;
        const float4 v = *reinterpret_cast<const float4*>(qbase + lq * HS_ + d4);
        Qs[(d4 + 0) * 64 + lq] = v.x;
        Qs[(d4 + 1) * 64 + lq] = v.y;
        Qs[(d4 + 2) * 64 + lq] = v.z;
        Qs[(d4 + 3) * 64 + lq] = v.w;
    }

    float y[4][4] = {};

    for (int kt = 0; kt <= qt; kt++) {
        const float* kbase = g_K + head_base + (size_t)kt * 64 * HS_;
        const float* vbase = g_V + head_base + (size_t)kt * 64 * HS_;

        #pragma unroll
        for (int l = 0; l < 4; l++) {
            const int d4 = lc + l * 16;
            const float4 kv = *reinterpret_cast<const float4*>(kbase + lq * HS_ + d4);
            Ks[(d4 + 0) * 64 + lq] = kv.x;
            Ks[(d4 + 1) * 64 + lq] = kv.y;
            Ks[(d4 + 2) * 64 + lq] = kv.z;
            Ks[(d4 + 3) * 64 + lq] = kv.w;
            const float4 vv = *reinterpret_cast<const float4*>(vbase + lq * HS_ + d4);
            *reinterpret_cast<float4*>(Vs + lq * 64 + d4) = vv;
        }
        __syncthreads();

        float s[4][4] = {};
        #pragma unroll
        for (int d = 0; d < 64; d++) {
            const float4 a  = *reinterpret_cast<const float4*>(Qs + d * 64 + ty * 4);
            const float4 bb = *reinterpret_cast<const float4*>(Ks + d * 64 + tx * 4);
            const float ar[4] = {a.x, a.y, a.z, a.w};
            const float br[4] = {bb.x, bb.y, bb.z, bb.w};
            #pragma unroll
            for (int i = 0; i < 4; i++)
                #pragma unroll
                for (int j = 0; j < 4; j++)
                    s[i][j] = fmaf(ar[i], br[j], s[i][j]);
        }

        const bool diag = (kt == qt);
        #pragma unroll
        for (int i = 0; i < 4; i++) {
            const int q = ty * 4 + i;
            float4 v;
            float* sv = &v.x;
            #pragma unroll
            for (int j = 0; j < 4; j++) {
                const int k = tx * 4 + j;
                float val = fmaxf(s[i][j] * scale, 0.0f);
                if (diag && k > q) val = 0.0f;
                sv[j] = val;
            }
            *reinterpret_cast<float4*>(Ss + q * 64 + tx * 4) = v;
        }
        __syncthreads();

        #pragma unroll
        for (int k = 0; k < 64; k++) {
            const float a0 = Ss[(ty * 4 + 0) * 64 + k];
            const float a1 = Ss[(ty * 4 + 1) * 64 + k];
            const float a2 = Ss[(ty * 4 + 2) * 64 + k];
            const float a3 = Ss[(ty * 4 + 3) * 64 + k];
            const float4 vv = *reinterpret_cast<const float4*>(Vs + k * 64 + tx * 4);
            const float vr[4] = {vv.x, vv.y, vv.z, vv.w};
            #pragma unroll
            for (int j = 0; j < 4; j++) {
                y[0][j] = fmaf(a0, vr[j], y[0][j]);
                y[1][j] = fmaf(a1, vr[j], y[1][j]);
                y[2][j] = fmaf(a2, vr[j], y[2][j]);
                y[3][j] = fmaf(a3, vr[j], y[3][j]);
            }
        }
        __syncthreads();
    }

    #pragma unroll
    for (int i = 0; i < 4; i++) {
        const int t = qt * 64 + ty * 4 + i;
        float4 v;
        v.x = y[i][0]; v.y = y[i][1]; v.z = y[i][2]; v.w = y[i][3];
        float* p = out + ((size_t)b * T_ + t) * C_ + h * HS_ + tx * 4;
        *reinterpret_cast<float4*>(p) = v;
    }
}

// ---------------------------------------------------------------------------
extern "C" void kernel_launch(void* const* d_in, const int* in_sizes, int n_in,
                              void* d_out, int out_size)
{
    const float* x    = (const float*)d_in[0];   // [8,1024,768]
    const float* W    = (const float*)d_in[1];   // [2304,768]
    const float* bias = (const float*)d_in[2];   // [2304]
    float* out = (float*)d_out;                  // [8,1024,768]

    // 0) fp32 -> bf16 hi/lo split
    split_kernel<<<1184, 256>>>(x, W);

    // 1) HMMA QKV GEMM: grid (N/128, M/128) = (18, 64)
    qkv_hmma_kernel<<<dim3(N_TOT / 128, M_TOT / 128), 256>>>(bias);

    // 2) attention: grid (B*H, T/64) = (96, 16), 64 KB dynamic smem
    cudaFuncSetAttribute(attn_kernel,
                         cudaFuncAttributeMaxDynamicSharedMemorySize, 65536);
    attn_kernel<<<dim3(B_ * H_, T_ / 64), 256, 65536>>>(out);
}

// round 4
// speedup vs baseline: 2.5115x; 1.6314x over previous
#include <cuda_runtime.h>
#include <cuda_bf16.h>
#include <cstdint>

// Problem constants
#define B_  8
#define T_  1024
#define C_  768
#define H_  12
#define HS_ 64
#define M_TOT (B_*T_)        // 8192
#define N_TOT (3*C_)         // 2304
#define K_TOT C_             // 768

// ---------------------------------------------------------------------------
// Device-global scratch: pre-split bf16 hi/lo Q, K, V in [B,H,T,hs] layout
// ---------------------------------------------------------------------------
__device__ __align__(16) __nv_bfloat16 g_Qh[B_*H_*T_*HS_];
__device__ __align__(16) __nv_bfloat16 g_Ql[B_*H_*T_*HS_];
__device__ __align__(16) __nv_bfloat16 g_Kh[B_*H_*T_*HS_];
__device__ __align__(16) __nv_bfloat16 g_Kl[B_*H_*T_*HS_];
__device__ __align__(16) __nv_bfloat16 g_Vh[B_*H_*T_*HS_];
__device__ __align__(16) __nv_bfloat16 g_Vl[B_*H_*T_*HS_];

__device__ __align__(16) __nv_bfloat16 g_xh[M_TOT*K_TOT];
__device__ __align__(16) __nv_bfloat16 g_xl[M_TOT*K_TOT];
__device__ __align__(16) __nv_bfloat16 g_wh[N_TOT*K_TOT];
__device__ __align__(16) __nv_bfloat16 g_wl[N_TOT*K_TOT];

// ---------------------------------------------------------------------------
// PTX helpers (base ISA only: sm_80-level, no 'a'-suffix features)
// ---------------------------------------------------------------------------
__device__ __forceinline__ uint32_t smem_u32(const void* p) {
    uint32_t a;
    asm("{ .reg .u64 t; cvta.to.shared.u64 t, %1; cvt.u32.u64 %0, t; }"
        : "=r"(a) : "l"(p));
    return a;
}
__device__ __forceinline__ void cp_async16(uint32_t s, const void* g) {
    asm volatile("cp.async.cg.shared.global [%0], [%1], 16;" :: "r"(s), "l"(g));
}
__device__ __forceinline__ void cp_commit() {
    asm volatile("cp.async.commit_group;" ::: "memory");
}
__device__ __forceinline__ void cp_wait1() {
    asm volatile("cp.async.wait_group 1;" ::: "memory");
}
__device__ __forceinline__ void cp_wait0() {
    asm volatile("cp.async.wait_group 0;" ::: "memory");
}
__device__ __forceinline__ void ldmatrix_x4(uint32_t& r0, uint32_t& r1,
                                            uint32_t& r2, uint32_t& r3,
                                            uint32_t addr) {
    asm volatile("ldmatrix.sync.aligned.m8n8.x4.shared.b16 {%0,%1,%2,%3}, [%4];"
                 : "=r"(r0), "=r"(r1), "=r"(r2), "=r"(r3) : "r"(addr));
}
__device__ __forceinline__ void ldmatrix_x4_trans(uint32_t& r0, uint32_t& r1,
                                                  uint32_t& r2, uint32_t& r3,
                                                  uint32_t addr) {
    asm volatile("ldmatrix.sync.aligned.m8n8.x4.trans.shared.b16 {%0,%1,%2,%3}, [%4];"
                 : "=r"(r0), "=r"(r1), "=r"(r2), "=r"(r3) : "r"(addr));
}
__device__ __forceinline__ void mma_bf16(float& c0, float& c1, float& c2, float& c3,
                                         uint32_t a0, uint32_t a1, uint32_t a2, uint32_t a3,
                                         uint32_t b0, uint32_t b1) {
    asm volatile(
        "mma.sync.aligned.m16n8k16.row.col.f32.bf16.bf16.f32 "
        "{%0,%1,%2,%3}, {%4,%5,%6,%7}, {%8,%9}, {%0,%1,%2,%3};"
        : "+f"(c0), "+f"(c1), "+f"(c2), "+f"(c3)
        : "r"(a0), "r"(a1), "r"(a2), "r"(a3), "r"(b0), "r"(b1));
}
__device__ __forceinline__ uint32_t pk_bf2(__nv_bfloat16 lo, __nv_bfloat16 hi) {
    __nv_bfloat162 v = __halves2bfloat162(lo, hi);
    return *reinterpret_cast<uint32_t*>(&v);
}
// swizzle for 128B-row tiles: 16B chunk c' = c ^ (row & 7)
#define SWZ128(o) ((o) ^ (((o) >> 3) & 0x70))

// ---------------------------------------------------------------------------
// Kernel 0: fp32 -> (bf16 hi, bf16 lo) split for x and W
// ---------------------------------------------------------------------------
__global__ __launch_bounds__(256) void split_kernel(const float* __restrict__ x,
                                                    const float* __restrict__ W)
{
    const int nqx = (M_TOT * K_TOT) / 4;
    const int nqw = (N_TOT * K_TOT) / 4;
    for (int q = blockIdx.x * blockDim.x + threadIdx.x; q < nqx + nqw;
         q += gridDim.x * blockDim.x) {
        const float4* src; __nv_bfloat16 *dh, *dl; int qq;
        if (q < nqx) { src = (const float4*)x; dh = g_xh; dl = g_xl; qq = q; }
        else         { src = (const float4*)W; dh = g_wh; dl = g_wl; qq = q - nqx; }
        const float4 v = src[qq];
        __nv_bfloat16 h0 = __float2bfloat16(v.x);
        __nv_bfloat16 h1 = __float2bfloat16(v.y);
        __nv_bfloat16 h2 = __float2bfloat16(v.z);
        __nv_bfloat16 h3 = __float2bfloat16(v.w);
        __nv_bfloat16 l0 = __float2bfloat16(v.x - __bfloat162float(h0));
        __nv_bfloat16 l1 = __float2bfloat16(v.y - __bfloat162float(h1));
        __nv_bfloat16 l2 = __float2bfloat16(v.z - __bfloat162float(h2));
        __nv_bfloat16 l3 = __float2bfloat16(v.w - __bfloat162float(h3));
        __nv_bfloat162* ph = (__nv_bfloat162*)(dh + (size_t)qq * 4);
        __nv_bfloat162* pl = (__nv_bfloat162*)(dl + (size_t)qq * 4);
        ph[0] = __halves2bfloat162(h0, h1);
        ph[1] = __halves2bfloat162(h2, h3);
        pl[0] = __halves2bfloat162(l0, l1);
        pl[1] = __halves2bfloat162(l2, l3);
    }
}

// ---------------------------------------------------------------------------
// Kernel 1: HMMA QKV GEMM, bf16-split x3; epilogue emits split bf16 Q/K/V.
// ---------------------------------------------------------------------------
#define ROWB 80
#define TILE_B (128*ROWB)
#define BUF_B  (2*TILE_B)
#define NITER  72

__global__ __launch_bounds__(256) void qkv_hmma_kernel(const float* __restrict__ bias)
{
    __shared__ __align__(16) char sm[2 * BUF_B];

    const int tid  = threadIdx.x;
    const int warp = tid >> 5;
    const int lane = tid & 31;
    const int m0 = blockIdx.y * 128;
    const int n0 = blockIdx.x * 128;
    const int wm0 = (warp >> 2) * 64;
    const int wn0 = (warp & 3) * 32;
    const uint32_t sbase = smem_u32(sm);

    auto fill = [&](int it, int buf) {
        const int pass = it / 24;
        const int kc   = (it - pass * 24) * 32;
        const __nv_bfloat16* Asrc = (pass < 2)  ? g_xh : g_xl;
        const __nv_bfloat16* Bsrc = (pass == 1) ? g_wl : g_wh;
        const uint32_t sA = sbase + buf * BUF_B;
        const uint32_t sB = sA + TILE_B;
        #pragma unroll
        for (int j = 0; j < 2; j++) {
            const int seg = tid + j * 256;
            const int r = seg >> 2, c = seg & 3;
            cp_async16(sA + r * ROWB + c * 16,
                       Asrc + (size_t)(m0 + r) * K_TOT + kc + c * 8);
            cp_async16(sB + r * ROWB + c * 16,
                       Bsrc + (size_t)(n0 + r) * K_TOT + kc + c * 8);
        }
        cp_commit();
    };

    float acc[4][4][4] = {};

    fill(0, 0);

    for (int i = 0; i < NITER; i++) {
        const int buf = i & 1;
        if (i + 1 < NITER) fill(i + 1, buf ^ 1);
        if (i + 1 < NITER) cp_wait1(); else cp_wait0();
        __syncthreads();

        const uint32_t sA = sbase + buf * BUF_B;
        const uint32_t sB = sA + TILE_B;

        uint32_t bf[4][4];
        #pragma unroll
        for (int nt = 0; nt < 4; nt++) {
            const int rrow = wn0 + nt * 8 + (lane & 7);
            const int col  = (lane >> 3) * 8;
            ldmatrix_x4(bf[nt][0], bf[nt][1], bf[nt][2], bf[nt][3],
                        sB + rrow * ROWB + col * 2);
        }
        #pragma unroll
        for (int ks = 0; ks < 2; ks++) {
            #pragma unroll
            for (int mt = 0; mt < 4; mt++) {
                uint32_t a0, a1, a2, a3;
                const int arow = wm0 + mt * 16 + (lane & 15);
                const int acol = ks * 16 + (lane >> 4) * 8;
                ldmatrix_x4(a0, a1, a2, a3, sA + arow * ROWB + acol * 2);
                #pragma unroll
                for (int nt = 0; nt < 4; nt++) {
                    mma_bf16(acc[mt][nt][0], acc[mt][nt][1],
                             acc[mt][nt][2], acc[mt][nt][3],
                             a0, a1, a2, a3,
                             bf[nt][ks * 2 + 0], bf[nt][ks * 2 + 1]);
                }
            }
        }
        __syncthreads();
    }

    // Epilogue: bias add + split to bf16 hi/lo, scatter [B,H,T,hs]
    const int g  = lane >> 2;
    const int tq = lane & 3;
    #pragma unroll
    for (int nt = 0; nt < 4; nt++) {
        const int n = n0 + wn0 + nt * 8 + tq * 2;
        const float b0 = __ldg(bias + n);
        const float b1 = __ldg(bias + n + 1);
        const int three = n / C_;
        const int rem   = n - three * C_;
        const int head  = rem >> 6;
        const int d     = rem & 63;
        __nv_bfloat16* dh = (three == 0) ? g_Qh : (three == 1) ? g_Kh : g_Vh;
        __nv_bfloat16* dl = (three == 0) ? g_Ql : (three == 1) ? g_Kl : g_Vl;
        #pragma unroll
        for (int mt = 0; mt < 4; mt++) {
            #pragma unroll
            for (int half = 0; half < 2; half++) {
                const int m = m0 + wm0 + mt * 16 + g + half * 8;
                const int bb = m >> 10;
                const int t  = m & 1023;
                const float f0 = acc[mt][nt][half * 2 + 0] + b0;
                const float f1 = acc[mt][nt][half * 2 + 1] + b1;
                const __nv_bfloat16 h0 = __float2bfloat16(f0);
                const __nv_bfloat16 h1 = __float2bfloat16(f1);
                const __nv_bfloat16 l0 = __float2bfloat16(f0 - __bfloat162float(h0));
                const __nv_bfloat16 l1 = __float2bfloat16(f1 - __bfloat162float(h1));
                const size_t idx = ((size_t)(bb * H_ + head) * T_ + t) * HS_ + d;
                *reinterpret_cast<__nv_bfloat162*>(dh + idx) = __halves2bfloat162(h0, h1);
                *reinterpret_cast<__nv_bfloat162*>(dl + idx) = __halves2bfloat162(l0, l1);
            }
        }
    }
}

// ---------------------------------------------------------------------------
// Kernel 2: fused causal ReLU attention on HMMA (bf16-split x3 both GEMMs).
// CTA = (b*H+h, qtile of 64). 128 threads = 4 warps, warp = 16 q-rows.
// smem: Qh|Ql (16KB) + 2 x (Kh|Kl|Vh|Vl) buffers (2 x 32KB) = 80KB.
// ---------------------------------------------------------------------------
#define AT_BUF0  16384
#define AT_BUF_B 32768
#define AT_SMEM  81920

__global__ __launch_bounds__(128) void attn_hmma_kernel(float* __restrict__ out)
{
    extern __shared__ char smema[];
    const uint32_t sb = smem_u32(smema);
    const int tid  = threadIdx.x;
    const int warp = tid >> 5;
    const int lane = tid & 31;
    const int bh = blockIdx.x;
    const int qt = blockIdx.y;
    const int b  = bh / H_;
    const int h  = bh - b * H_;
    const size_t hbase = (size_t)bh * T_ * HS_;

    // ---- load Q tile (hi+lo), swizzled
    {
        #pragma unroll
        for (int j = 0; j < 8; j++) {
            const int seg = tid + j * 128;          // 0..1023
            const int arr = seg >> 9;               // 0:Qh 1:Ql
            const int w = seg & 511;
            const int r = w >> 3, c = w & 7;
            const __nv_bfloat16* src = arr ? g_Ql : g_Qh;
            cp_async16(sb + arr * 8192 + SWZ128(r * 128 + c * 16),
                       src + hbase + (size_t)(qt * 64 + r) * HS_ + c * 8);
        }
    }
    auto fillkv = [&](int kt, int buf) {
        #pragma unroll
        for (int j = 0; j < 16; j++) {
            const int seg = tid + j * 128;          // 0..2047
            const int arr = seg >> 9;               // 0:Kh 1:Kl 2:Vh 3:Vl
            const int w = seg & 511;
            const int r = w >> 3, c = w & 7;
            const __nv_bfloat16* src = (arr == 0) ? g_Kh : (arr == 1) ? g_Kl
                                     : (arr == 2) ? g_Vh : g_Vl;
            cp_async16(sb + AT_BUF0 + buf * AT_BUF_B + arr * 8192
                           + SWZ128(r * 128 + c * 16),
                       src + hbase + (size_t)(kt * 64 + r) * HS_ + c * 8);
        }
        cp_commit();
    };

    fillkv(0, 0);   // Q loads ride in this group

    float y[8][4] = {};
    const float scale = 0.125f;
    const int rlo = warp * 16 + (lane >> 2);   // local q row (c0/c1)
    const int cbase = 2 * (lane & 3);

    for (int kt = 0; kt <= qt; kt++) {
        const int buf = kt & 1;
        if (kt < qt) { fillkv(kt + 1, buf ^ 1); cp_wait1(); }
        else         { cp_wait0(); }
        __syncthreads();

        const uint32_t sQh = sb, sQl = sb + 8192;
        const uint32_t sK0 = sb + AT_BUF0 + buf * AT_BUF_B;
        const uint32_t sKh = sK0, sKl = sK0 + 8192;
        const uint32_t sVh = sK0 + 16384, sVl = sK0 + 24576;

        // ---- S = Q·K^T, 3-pass split
        float S[8][4] = {};
        #pragma unroll
        for (int p = 0; p < 3; p++) {
            const uint32_t qb = (p == 2) ? sQl : sQh;
            const uint32_t kb = (p == 1) ? sKl : sKh;
            uint32_t af[4][4];
            #pragma unroll
            for (int ks = 0; ks < 4; ks++) {
                const int row = warp * 16 + (lane & 15);
                const int colb = ks * 32 + (lane >> 4) * 16;
                ldmatrix_x4(af[ks][0], af[ks][1], af[ks][2], af[ks][3],
                            qb + SWZ128(row * 128 + colb));
            }
            #pragma unroll
            for (int nt = 0; nt < 8; nt++) {
                #pragma unroll
                for (int kp = 0; kp < 2; kp++) {
                    uint32_t b0, b1, b2, b3;
                    const int row = nt * 8 + (lane & 7);
                    const int colb = kp * 64 + (lane >> 3) * 16;
                    ldmatrix_x4(b0, b1, b2, b3, kb + SWZ128(row * 128 + colb));
                    mma_bf16(S[nt][0], S[nt][1], S[nt][2], S[nt][3],
                             af[2*kp][0], af[2*kp][1], af[2*kp][2], af[2*kp][3],
                             b0, b1);
                    mma_bf16(S[nt][0], S[nt][1], S[nt][2], S[nt][3],
                             af[2*kp+1][0], af[2*kp+1][1], af[2*kp+1][2], af[2*kp+1][3],
                             b2, b3);
                }
            }
        }

        // ---- P = relu(scale*S), causal mask on diag tile; split + repack to A frags
        const bool diag = (kt == qt);
        uint32_t pha[4][4], pla[4][4];
        #pragma unroll
        for (int ksp = 0; ksp < 4; ksp++) {
            #pragma unroll
            for (int u = 0; u < 2; u++) {
                const int ntile = 2 * ksp + u;
                float pv[4];
                #pragma unroll
                for (int c = 0; c < 4; c++) {
                    float v = fmaxf(S[ntile][c] * scale, 0.0f);
                    if (diag) {
                        const int col = ntile * 8 + cbase + (c & 1);
                        const int row = rlo + ((c >= 2) ? 8 : 0);
                        if (col > row) v = 0.0f;
                    }
                    pv[c] = v;
                }
                __nv_bfloat16 h0 = __float2bfloat16(pv[0]);
                __nv_bfloat16 h1 = __float2bfloat16(pv[1]);
                __nv_bfloat16 h2 = __float2bfloat16(pv[2]);
                __nv_bfloat16 h3 = __float2bfloat16(pv[3]);
                pha[ksp][2*u + 0] = pk_bf2(h0, h1);
                pha[ksp][2*u + 1] = pk_bf2(h2, h3);
                pla[ksp][2*u + 0] = pk_bf2(
                    __float2bfloat16(pv[0] - __bfloat162float(h0)),
                    __float2bfloat16(pv[1] - __bfloat162float(h1)));
                pla[ksp][2*u + 1] = pk_bf2(
                    __float2bfloat16(pv[2] - __bfloat162float(h2)),
                    __float2bfloat16(pv[3] - __bfloat162float(h3)));
            }
        }

        // ---- y += P·V, 3-pass split; V frags via ldmatrix.trans (V is [t][d])
        #pragma unroll
        for (int p = 0; p < 3; p++) {
            const uint32_t vb = (p == 1) ? sVl : sVh;
            const uint32_t (*pa)[4] = (p == 2) ? pla : pha;
            #pragma unroll
            for (int nt = 0; nt < 8; nt++) {
                #pragma unroll
                for (int kp = 0; kp < 2; kp++) {
                    uint32_t b0, b1, b2, b3;
                    const int row = kp * 32 + (lane >> 3) * 8 + (lane & 7);
                    const int colb = nt * 16;
                    ldmatrix_x4_trans(b0, b1, b2, b3, vb + SWZ128(row * 128 + colb));
                    mma_bf16(y[nt][0], y[nt][1], y[nt][2], y[nt][3],
                             pa[2*kp][0], pa[2*kp][1], pa[2*kp][2], pa[2*kp][3],
                             b0, b1);
                    mma_bf16(y[nt][0], y[nt][1], y[nt][2], y[nt][3],
                             pa[2*kp+1][0], pa[2*kp+1][1], pa[2*kp+1][2], pa[2*kp+1][3],
                             b2, b3);
                }
            }
        }
        __syncthreads();   // all reads of this buffer done before next fill
    }

    // ---- epilogue: y -> out[b, t, h*64 + d]
    const int g = lane >> 2;
    #pragma unroll
    for (int nt = 0; nt < 8; nt++) {
        const int col = h * HS_ + nt * 8 + cbase;
        const int t0 = qt * 64 + warp * 16 + g;
        float2 v0; v0.x = y[nt][0]; v0.y = y[nt][1];
        float2 v1; v1.x = y[nt][2]; v1.y = y[nt][3];
        *reinterpret_cast<float2*>(out + ((size_t)b * T_ + t0) * C_ + col) = v0;
        *reinterpret_cast<float2*>(out + ((size_t)b * T_ + t0 + 8) * C_ + col) = v1;
    }
}

// ---------------------------------------------------------------------------
extern "C" void kernel_launch(void* const* d_in, const int* in_sizes, int n_in,
                              void* d_out, int out_size)
{
    const float* x    = (const float*)d_in[0];
    const float* W    = (const float*)d_in[1];
    const float* bias = (const float*)d_in[2];
    float* out = (float*)d_out;

    split_kernel<<<1184, 256>>>(x, W);

    qkv_hmma_kernel<<<dim3(N_TOT / 128, M_TOT / 128), 256>>>(bias);

    cudaFuncSetAttribute(attn_hmma_kernel,
                         cudaFuncAttributeMaxDynamicSharedMemorySize, AT_SMEM);
    attn_hmma_kernel<<<dim3(B_ * H_, T_ / 64), 128, AT_SMEM>>>(out);
}

// round 5
// speedup vs baseline: 2.7154x; 1.0812x over previous
#include <cuda_runtime.h>
#include <cuda_bf16.h>
#include <cstdint>

// Problem constants
#define B_  8
#define T_  1024
#define C_  768
#define H_  12
#define HS_ 64
#define M_TOT (B_*T_)        // 8192
#define N_TOT (3*C_)         // 2304
#define K_TOT C_             // 768

// ---------------------------------------------------------------------------
// Device-global scratch: pre-split bf16 hi/lo Q, K, V in [B,H,T,hs] layout
// ---------------------------------------------------------------------------
__device__ __align__(16) __nv_bfloat16 g_Qh[B_*H_*T_*HS_];
__device__ __align__(16) __nv_bfloat16 g_Ql[B_*H_*T_*HS_];
__device__ __align__(16) __nv_bfloat16 g_Kh[B_*H_*T_*HS_];
__device__ __align__(16) __nv_bfloat16 g_Kl[B_*H_*T_*HS_];
__device__ __align__(16) __nv_bfloat16 g_Vh[B_*H_*T_*HS_];
__device__ __align__(16) __nv_bfloat16 g_Vl[B_*H_*T_*HS_];

__device__ __align__(16) __nv_bfloat16 g_xh[M_TOT*K_TOT];
__device__ __align__(16) __nv_bfloat16 g_xl[M_TOT*K_TOT];
__device__ __align__(16) __nv_bfloat16 g_wh[N_TOT*K_TOT];
__device__ __align__(16) __nv_bfloat16 g_wl[N_TOT*K_TOT];

// ---------------------------------------------------------------------------
// PTX helpers (base ISA only)
// ---------------------------------------------------------------------------
__device__ __forceinline__ uint32_t smem_u32(const void* p) {
    uint32_t a;
    asm("{ .reg .u64 t; cvta.to.shared.u64 t, %1; cvt.u32.u64 %0, t; }"
        : "=r"(a) : "l"(p));
    return a;
}
__device__ __forceinline__ void cp_async16(uint32_t s, const void* g) {
    asm volatile("cp.async.cg.shared.global [%0], [%1], 16;" :: "r"(s), "l"(g));
}
__device__ __forceinline__ void cp_commit() {
    asm volatile("cp.async.commit_group;" ::: "memory");
}
__device__ __forceinline__ void cp_wait1() {
    asm volatile("cp.async.wait_group 1;" ::: "memory");
}
__device__ __forceinline__ void cp_wait0() {
    asm volatile("cp.async.wait_group 0;" ::: "memory");
}
__device__ __forceinline__ void ldmatrix_x4(uint32_t& r0, uint32_t& r1,
                                            uint32_t& r2, uint32_t& r3,
                                            uint32_t addr) {
    asm volatile("ldmatrix.sync.aligned.m8n8.x4.shared.b16 {%0,%1,%2,%3}, [%4];"
                 : "=r"(r0), "=r"(r1), "=r"(r2), "=r"(r3) : "r"(addr));
}
__device__ __forceinline__ void ldmatrix_x4_trans(uint32_t& r0, uint32_t& r1,
                                                  uint32_t& r2, uint32_t& r3,
                                                  uint32_t addr) {
    asm volatile("ldmatrix.sync.aligned.m8n8.x4.trans.shared.b16 {%0,%1,%2,%3}, [%4];"
                 : "=r"(r0), "=r"(r1), "=r"(r2), "=r"(r3) : "r"(addr));
}
__device__ __forceinline__ void mma_bf16(float& c0, float& c1, float& c2, float& c3,
                                         uint32_t a0, uint32_t a1, uint32_t a2, uint32_t a3,
                                         uint32_t b0, uint32_t b1) {
    asm volatile(
        "mma.sync.aligned.m16n8k16.row.col.f32.bf16.bf16.f32 "
        "{%0,%1,%2,%3}, {%4,%5,%6,%7}, {%8,%9}, {%0,%1,%2,%3};"
        : "+f"(c0), "+f"(c1), "+f"(c2), "+f"(c3)
        : "r"(a0), "r"(a1), "r"(a2), "r"(a3), "r"(b0), "r"(b1));
}
__device__ __forceinline__ uint32_t pk_bf2(__nv_bfloat16 lo, __nv_bfloat16 hi) {
    __nv_bfloat162 v = __halves2bfloat162(lo, hi);
    return *reinterpret_cast<uint32_t*>(&v);
}
#define SWZ128(o) ((o) ^ (((o) >> 3) & 0x70))

// ---------------------------------------------------------------------------
// Kernel 0: fp32 -> (bf16 hi, bf16 lo) split for x and W
// ---------------------------------------------------------------------------
__global__ __launch_bounds__(256) void split_kernel(const float* __restrict__ x,
                                                    const float* __restrict__ W)
{
    const int nqx = (M_TOT * K_TOT) / 4;
    const int nqw = (N_TOT * K_TOT) / 4;
    for (int q = blockIdx.x * blockDim.x + threadIdx.x; q < nqx + nqw;
         q += gridDim.x * blockDim.x) {
        const float4* src; __nv_bfloat16 *dh, *dl; int qq;
        if (q < nqx) { src = (const float4*)x; dh = g_xh; dl = g_xl; qq = q; }
        else         { src = (const float4*)W; dh = g_wh; dl = g_wl; qq = q - nqx; }
        const float4 v = src[qq];
        __nv_bfloat16 h0 = __float2bfloat16(v.x);
        __nv_bfloat16 h1 = __float2bfloat16(v.y);
        __nv_bfloat16 h2 = __float2bfloat16(v.z);
        __nv_bfloat16 h3 = __float2bfloat16(v.w);
        __nv_bfloat16 l0 = __float2bfloat16(v.x - __bfloat162float(h0));
        __nv_bfloat16 l1 = __float2bfloat16(v.y - __bfloat162float(h1));
        __nv_bfloat16 l2 = __float2bfloat16(v.z - __bfloat162float(h2));
        __nv_bfloat16 l3 = __float2bfloat16(v.w - __bfloat162float(h3));
        __nv_bfloat162* ph = (__nv_bfloat162*)(dh + (size_t)qq * 4);
        __nv_bfloat162* pl = (__nv_bfloat162*)(dl + (size_t)qq * 4);
        ph[0] = __halves2bfloat162(h0, h1);
        ph[1] = __halves2bfloat162(h2, h3);
        pl[0] = __halves2bfloat162(l0, l1);
        pl[1] = __halves2bfloat162(l2, l3);
    }
}

// ---------------------------------------------------------------------------
// Kernel 1: HMMA QKV GEMM v2 — single k-sweep, 3 fused precision passes.
// Per 32-wide k-chunk, smem holds Ah|Al|Bh|Bl; issue Ah·Bh + Ah·Bl + Al·Bh.
// CTA tile 128x128, 256 threads = 8 warps (2m x 4n), warp tile 64x32.
// ---------------------------------------------------------------------------
#define ROWB 80
#define TILE_B (128*ROWB)       // 10240 B per operand tile
#define BUF_B  (4*TILE_B)       // Ah+Al+Bh+Bl per buffer = 40960 B
#define GEMM_SMEM (2*BUF_B)     // 81920 B
#define NITER  24               // k chunks of 32

__global__ __launch_bounds__(256) void qkv_hmma_kernel(const float* __restrict__ bias)
{
    extern __shared__ char smg[];
    const uint32_t sbase = smem_u32(smg);

    const int tid  = threadIdx.x;
    const int warp = tid >> 5;
    const int lane = tid & 31;
    const int m0 = blockIdx.y * 128;
    const int n0 = blockIdx.x * 128;
    const int wm0 = (warp >> 2) * 64;
    const int wn0 = (warp & 3) * 32;

    // fill one k-chunk: Ah, Al (rows m0..), Bh, Bl (rows n0..)
    auto fill = [&](int it, int buf) {
        const int kc = it * 32;
        const uint32_t base = sbase + buf * BUF_B;
        #pragma unroll
        for (int j = 0; j < 8; j++) {
            const int seg = tid + j * 256;        // 0..2047
            const int arr = seg >> 9;             // 0:Ah 1:Al 2:Bh 3:Bl
            const int w = seg & 511;
            const int r = w >> 2, c = w & 3;      // row 0..127, 16B chunk 0..3
            const __nv_bfloat16* src = (arr == 0) ? g_xh : (arr == 1) ? g_xl
                                     : (arr == 2) ? g_wh : g_wl;
            const int row = ((arr < 2) ? m0 : n0) + r;
            cp_async16(base + arr * TILE_B + r * ROWB + c * 16,
                       src + (size_t)row * K_TOT + kc + c * 8);
        }
        cp_commit();
    };

    float acc[4][4][4] = {};

    fill(0, 0);

    for (int i = 0; i < NITER; i++) {
        const int buf = i & 1;
        if (i + 1 < NITER) fill(i + 1, buf ^ 1);
        if (i + 1 < NITER) cp_wait1(); else cp_wait0();
        __syncthreads();

        const uint32_t sAh = sbase + buf * BUF_B;
        const uint32_t sAl = sAh + TILE_B;
        const uint32_t sBh = sAh + 2 * TILE_B;
        const uint32_t sBl = sAh + 3 * TILE_B;

        // B fragments for hi and lo (each x4 covers both 16-k steps)
        uint32_t bh[4][4], bl[4][4];
        #pragma unroll
        for (int nt = 0; nt < 4; nt++) {
            const int off = (wn0 + nt * 8 + (lane & 7)) * ROWB + (lane >> 3) * 16;
            ldmatrix_x4(bh[nt][0], bh[nt][1], bh[nt][2], bh[nt][3], sBh + off);
            ldmatrix_x4(bl[nt][0], bl[nt][1], bl[nt][2], bl[nt][3], sBl + off);
        }

        #pragma unroll
        for (int ks = 0; ks < 2; ks++) {
            #pragma unroll
            for (int mt = 0; mt < 4; mt++) {
                const int off = (wm0 + mt * 16 + (lane & 15)) * ROWB
                              + ks * 32 + (lane >> 4) * 16;
                uint32_t ah0, ah1, ah2, ah3, al0, al1, al2, al3;
                ldmatrix_x4(ah0, ah1, ah2, ah3, sAh + off);
                ldmatrix_x4(al0, al1, al2, al3, sAl + off);
                #pragma unroll
                for (int nt = 0; nt < 4; nt++) {
                    float* c = acc[mt][nt];
                    mma_bf16(c[0], c[1], c[2], c[3], ah0, ah1, ah2, ah3,
                             bh[nt][ks * 2 + 0], bh[nt][ks * 2 + 1]);
                    mma_bf16(c[0], c[1], c[2], c[3], ah0, ah1, ah2, ah3,
                             bl[nt][ks * 2 + 0], bl[nt][ks * 2 + 1]);
                    mma_bf16(c[0], c[1], c[2], c[3], al0, al1, al2, al3,
                             bh[nt][ks * 2 + 0], bh[nt][ks * 2 + 1]);
                }
            }
        }
        __syncthreads();
    }

    // Epilogue: bias add + split to bf16 hi/lo, scatter [B,H,T,hs]
    const int g  = lane >> 2;
    const int tq = lane & 3;
    #pragma unroll
    for (int nt = 0; nt < 4; nt++) {
        const int n = n0 + wn0 + nt * 8 + tq * 2;
        const float b0 = __ldg(bias + n);
        const float b1 = __ldg(bias + n + 1);
        const int three = n / C_;
        const int rem   = n - three * C_;
        const int head  = rem >> 6;
        const int d     = rem & 63;
        __nv_bfloat16* dh = (three == 0) ? g_Qh : (three == 1) ? g_Kh : g_Vh;
        __nv_bfloat16* dl = (three == 0) ? g_Ql : (three == 1) ? g_Kl : g_Vl;
        #pragma unroll
        for (int mt = 0; mt < 4; mt++) {
            #pragma unroll
            for (int half = 0; half < 2; half++) {
                const int m = m0 + wm0 + mt * 16 + g + half * 8;
                const int bb = m >> 10;
                const int t  = m & 1023;
                const float f0 = acc[mt][nt][half * 2 + 0] + b0;
                const float f1 = acc[mt][nt][half * 2 + 1] + b1;
                const __nv_bfloat16 h0 = __float2bfloat16(f0);
                const __nv_bfloat16 h1 = __float2bfloat16(f1);
                const __nv_bfloat16 l0 = __float2bfloat16(f0 - __bfloat162float(h0));
                const __nv_bfloat16 l1 = __float2bfloat16(f1 - __bfloat162float(h1));
                const size_t idx = ((size_t)(bb * H_ + head) * T_ + t) * HS_ + d;
                *reinterpret_cast<__nv_bfloat162*>(dh + idx) = __halves2bfloat162(h0, h1);
                *reinterpret_cast<__nv_bfloat162*>(dl + idx) = __halves2bfloat162(l0, l1);
            }
        }
    }
}

// ---------------------------------------------------------------------------
// Kernel 2: fused causal ReLU attention on HMMA (unchanged from R4)
// ---------------------------------------------------------------------------
#define AT_BUF0  16384
#define AT_BUF_B 32768
#define AT_SMEM  81920

__global__ __launch_bounds__(128) void attn_hmma_kernel(float* __restrict__ out)
{
    extern __shared__ char smema[];
    const uint32_t sb = smem_u32(smema);
    const int tid  = threadIdx.x;
    const int warp = tid >> 5;
    const int lane = tid & 31;
    const int bh = blockIdx.x;
    const int qt = blockIdx.y;
    const int b  = bh / H_;
    const int h  = bh - b * H_;
    const size_t hbase = (size_t)bh * T_ * HS_;

    {
        #pragma unroll
        for (int j = 0; j < 8; j++) {
            const int seg = tid + j * 128;
            const int arr = seg >> 9;
            const int w = seg & 511;
            const int r = w >> 3, c = w & 7;
            const __nv_bfloat16* src = arr ? g_Ql : g_Qh;
            cp_async16(sb + arr * 8192 + SWZ128(r * 128 + c * 16),
                       src + hbase + (size_t)(qt * 64 + r) * HS_ + c * 8);
        }
    }
    auto fillkv = [&](int kt, int buf) {
        #pragma unroll
        for (int j = 0; j < 16; j++) {
            const int seg = tid + j * 128;
            const int arr = seg >> 9;
            const int w = seg & 511;
            const int r = w >> 3, c = w & 7;
            const __nv_bfloat16* src = (arr == 0) ? g_Kh : (arr == 1) ? g_Kl
                                     : (arr == 2) ? g_Vh : g_Vl;
            cp_async16(sb + AT_BUF0 + buf * AT_BUF_B + arr * 8192
                           + SWZ128(r * 128 + c * 16),
                       src + hbase + (size_t)(kt * 64 + r) * HS_ + c * 8);
        }
        cp_commit();
    };

    fillkv(0, 0);

    float y[8][4] = {};
    const float scale = 0.125f;
    const int rlo = warp * 16 + (lane >> 2);
    const int cbase = 2 * (lane & 3);

    for (int kt = 0; kt <= qt; kt++) {
        const int buf = kt & 1;
        if (kt < qt) { fillkv(kt + 1, buf ^ 1); cp_wait1(); }
        else         { cp_wait0(); }
        __syncthreads();

        const uint32_t sQh = sb, sQl = sb + 8192;
        const uint32_t sK0 = sb + AT_BUF0 + buf * AT_BUF_B;
        const uint32_t sKh = sK0, sKl = sK0 + 8192;
        const uint32_t sVh = sK0 + 16384, sVl = sK0 + 24576;

        float S[8][4] = {};
        #pragma unroll
        for (int p = 0; p < 3; p++) {
            const uint32_t qb = (p == 2) ? sQl : sQh;
            const uint32_t kb = (p == 1) ? sKl : sKh;
            uint32_t af[4][4];
            #pragma unroll
            for (int ks = 0; ks < 4; ks++) {
                const int row = warp * 16 + (lane & 15);
                const int colb = ks * 32 + (lane >> 4) * 16;
                ldmatrix_x4(af[ks][0], af[ks][1], af[ks][2], af[ks][3],
                            qb + SWZ128(row * 128 + colb));
            }
            #pragma unroll
            for (int nt = 0; nt < 8; nt++) {
                #pragma unroll
                for (int kp = 0; kp < 2; kp++) {
                    uint32_t b0, b1, b2, b3;
                    const int row = nt * 8 + (lane & 7);
                    const int colb = kp * 64 + (lane >> 3) * 16;
                    ldmatrix_x4(b0, b1, b2, b3, kb + SWZ128(row * 128 + colb));
                    mma_bf16(S[nt][0], S[nt][1], S[nt][2], S[nt][3],
                             af[2*kp][0], af[2*kp][1], af[2*kp][2], af[2*kp][3],
                             b0, b1);
                    mma_bf16(S[nt][0], S[nt][1], S[nt][2], S[nt][3],
                             af[2*kp+1][0], af[2*kp+1][1], af[2*kp+1][2], af[2*kp+1][3],
                             b2, b3);
                }
            }
        }

        const bool diag = (kt == qt);
        uint32_t pha[4][4], pla[4][4];
        #pragma unroll
        for (int ksp = 0; ksp < 4; ksp++) {
            #pragma unroll
            for (int u = 0; u < 2; u++) {
                const int ntile = 2 * ksp + u;
                float pv[4];
                #pragma unroll
                for (int c = 0; c < 4; c++) {
                    float v = fmaxf(S[ntile][c] * scale, 0.0f);
                    if (diag) {
                        const int col = ntile * 8 + cbase + (c & 1);
                        const int row = rlo + ((c >= 2) ? 8 : 0);
                        if (col > row) v = 0.0f;
                    }
                    pv[c] = v;
                }
                __nv_bfloat16 h0 = __float2bfloat16(pv[0]);
                __nv_bfloat16 h1 = __float2bfloat16(pv[1]);
                __nv_bfloat16 h2 = __float2bfloat16(pv[2]);
                __nv_bfloat16 h3 = __float2bfloat16(pv[3]);
                pha[ksp][2*u + 0] = pk_bf2(h0, h1);
                pha[ksp][2*u + 1] = pk_bf2(h2, h3);
                pla[ksp][2*u + 0] = pk_bf2(
                    __float2bfloat16(pv[0] - __bfloat162float(h0)),
                    __float2bfloat16(pv[1] - __bfloat162float(h1)));
                pla[ksp][2*u + 1] = pk_bf2(
                    __float2bfloat16(pv[2] - __bfloat162float(h2)),
                    __float2bfloat16(pv[3] - __bfloat162float(h3)));
            }
        }

        #pragma unroll
        for (int p = 0; p < 3; p++) {
            const uint32_t vb = (p == 1) ? sVl : sVh;
            const uint32_t (*pa)[4] = (p == 2) ? pla : pha;
            #pragma unroll
            for (int nt = 0; nt < 8; nt++) {
                #pragma unroll
                for (int kp = 0; kp < 2; kp++) {
                    uint32_t b0, b1, b2, b3;
                    const int row = kp * 32 + (lane >> 3) * 8 + (lane & 7);
                    const int colb = nt * 16;
                    ldmatrix_x4_trans(b0, b1, b2, b3, vb + SWZ128(row * 128 + colb));
                    mma_bf16(y[nt][0], y[nt][1], y[nt][2], y[nt][3],
                             pa[2*kp][0], pa[2*kp][1], pa[2*kp][2], pa[2*kp][3],
                             b0, b1);
                    mma_bf16(y[nt][0], y[nt][1], y[nt][2], y[nt][3],
                             pa[2*kp+1][0], pa[2*kp+1][1], pa[2*kp+1][2], pa[2*kp+1][3],
                             b2, b3);
                }
            }
        }
        __syncthreads();
    }

    const int g = lane >> 2;
    #pragma unroll
    for (int nt = 0; nt < 8; nt++) {
        const int col = h * HS_ + nt * 8 + cbase;
        const int t0 = qt * 64 + warp * 16 + g;
        float2 v0; v0.x = y[nt][0]; v0.y = y[nt][1];
        float2 v1; v1.x = y[nt][2]; v1.y = y[nt][3];
        *reinterpret_cast<float2*>(out + ((size_t)b * T_ + t0) * C_ + col) = v0;
        *reinterpret_cast<float2*>(out + ((size_t)b * T_ + t0 + 8) * C_ + col) = v1;
    }
}

// ---------------------------------------------------------------------------
extern "C" void kernel_launch(void* const* d_in, const int* in_sizes, int n_in,
                              void* d_out, int out_size)
{
    const float* x    = (const float*)d_in[0];
    const float* W    = (const float*)d_in[1];
    const float* bias = (const float*)d_in[2];
    float* out = (float*)d_out;

    split_kernel<<<1184, 256>>>(x, W);

    cudaFuncSetAttribute(qkv_hmma_kernel,
                         cudaFuncAttributeMaxDynamicSharedMemorySize, GEMM_SMEM);
    qkv_hmma_kernel<<<dim3(N_TOT / 128, M_TOT / 128), 256, GEMM_SMEM>>>(bias);

    cudaFuncSetAttribute(attn_hmma_kernel,
                         cudaFuncAttributeMaxDynamicSharedMemorySize, AT_SMEM);
    attn_hmma_kernel<<<dim3(B_ * H_, T_ / 64), 128, AT_SMEM>>>(out);
}